// round 3
// baseline (speedup 1.0000x reference)
#include <cuda_runtime.h>
#include <math.h>

#define NN   512
#define CSd  384
#define CZd  128
#define Hd   12
#define Cd   16
#define PQd  4
#define PVd  8
#define DE   28
#define CATd 2017
#define MPROJ 1152
#define KSPLIT 4

typedef unsigned long long ull;

// ---------------- packed f32x2 helpers ----------------
__device__ __forceinline__ void ffma2(ull& acc, ull a, ull b) {
    asm("fma.rn.f32x2 %0, %1, %2, %0;" : "+l"(acc) : "l"(a), "l"(b));
}
__device__ __forceinline__ ull pk2(float x, float y) {
    ull r; asm("mov.b64 %0, {%1,%2};" : "=l"(r) : "f"(x), "f"(y)); return r;
}
__device__ __forceinline__ void upk2(ull v, float& x, float& y) {
    asm("mov.b64 {%0,%1}, %2;" : "=f"(x), "=f"(y) : "l"(v));
}

// ---------------- device scratch ----------------
__device__ float g_Wcat[MPROJ * CSd];
__device__ float g_P[MPROJ * NN];
__device__ float g_qe[Hd * DE * NN];
__device__ float g_ke[Hd * DE * NN];
__device__ float g_qn[Hd * NN];
__device__ float g_kn[Hd * NN];
__device__ float g_vr[Hd * Cd * NN];
__device__ float g_vg[3 * Hd * PVd * NN];
__device__ float g_A[NN * Hd * NN];          // probs [i][h][j]
__device__ float g_cat[CATd * NN];
__device__ float g_part[KSPLIT * CSd * NN];

// ---------------- weight concat ----------------
__global__ void concat_w(const float* __restrict__ Wq, const float* __restrict__ Wk,
                         const float* __restrict__ Wv, const float* __restrict__ Wqp,
                         const float* __restrict__ Wkp, const float* __restrict__ Wvp) {
    int idx = blockIdx.x * 256 + threadIdx.x;
    if (idx >= MPROJ * CSd) return;
    int row = idx / CSd, c = idx % CSd;
    float v;
    if      (row < 192) v = Wq [(row      ) * CSd + c];
    else if (row < 384) v = Wk [(row - 192) * CSd + c];
    else if (row < 576) v = Wv [(row - 384) * CSd + c];
    else if (row < 720) v = Wqp[(row - 576) * CSd + c];
    else if (row < 864) v = Wkp[(row - 720) * CSd + c];
    else                v = Wvp[(row - 864) * CSd + c];
    g_Wcat[idx] = v;
}

// ---------------- tiled GEMM with split-K, f32x2 inner ----------------
__global__ __launch_bounds__(256) void gemm64(const float* __restrict__ A,
                                              const float* __restrict__ B,
                                              float* __restrict__ C,
                                              int M, int Nc, int K) {
    int nb = blockIdx.x, mb = blockIdx.y, zb = blockIdx.z;
    int Kc = (K + gridDim.z - 1) / gridDim.z;
    int k0 = zb * Kc;
    int kend = min(K, k0 + Kc);

    __shared__ float As[16][64];
    __shared__ float Bs[16][64];

    int tid = threadIdx.x;
    int ty = tid >> 4, tx = tid & 15;
    ull acc2[2][4];   // (m-pair, n)
#pragma unroll
    for (int u = 0; u < 2; ++u)
#pragma unroll
        for (int v = 0; v < 4; ++v) acc2[u][v] = 0ull;

    for (int kk = k0; kk < kend; kk += 16) {
#pragma unroll
        for (int l = 0; l < 4; ++l) {
            int e = tid + l * 256;
            int m = e >> 4, k = e & 15;
            As[k][m] = (kk + k < kend) ? A[(size_t)(mb * 64 + m) * K + kk + k] : 0.f;
        }
#pragma unroll
        for (int l = 0; l < 4; ++l) {
            int e = tid + l * 256;
            int k = e >> 6, n = e & 63;
            Bs[k][n] = (kk + k < kend) ? B[(size_t)(kk + k) * Nc + nb * 64 + n] : 0.f;
        }
        __syncthreads();
#pragma unroll
        for (int k = 0; k < 16; ++k) {
            const ull* a2 = (const ull*)&As[k][ty * 4];   // (m0,m1) (m2,m3)
            float4 b = *(const float4*)&Bs[k][tx * 4];
            ull b0 = pk2(b.x, b.x), b1 = pk2(b.y, b.y);
            ull b2 = pk2(b.z, b.z), b3 = pk2(b.w, b.w);
            ull a0 = a2[0], a1 = a2[1];
            ffma2(acc2[0][0], a0, b0); ffma2(acc2[0][1], a0, b1);
            ffma2(acc2[0][2], a0, b2); ffma2(acc2[0][3], a0, b3);
            ffma2(acc2[1][0], a1, b0); ffma2(acc2[1][1], a1, b1);
            ffma2(acc2[1][2], a1, b2); ffma2(acc2[1][3], a1, b3);
        }
        __syncthreads();
    }
    float* Cz = C + (size_t)zb * M * Nc;
#pragma unroll
    for (int u = 0; u < 2; ++u)
#pragma unroll
        for (int v = 0; v < 4; ++v) {
            float lo, hi;
            upk2(acc2[u][v], lo, hi);
            Cz[(size_t)(mb * 64 + ty * 4 + u * 2    ) * Nc + nb * 64 + tx * 4 + v] = lo;
            Cz[(size_t)(mb * 64 + ty * 4 + u * 2 + 1) * Nc + nb * 64 + tx * 4 + v] = hi;
        }
}

// ---------------- prep: parallel over (h, i) ----------------
__global__ void prep_kernel(const float* __restrict__ t_r, const float* __restrict__ t_t,
                            const float* __restrict__ gamma) {
    int idx = blockIdx.x * 256 + threadIdx.x;
    if (idx >= Hd * NN) return;
    int h = idx / NN, i = idx % NN;
    const float w_c = 0.23570226039551584f;
    float R[9], T[3];
#pragma unroll
    for (int r = 0; r < 9; ++r) R[r] = t_r[i * 9 + r];
#pragma unroll
    for (int c = 0; c < 3; ++c) T[c] = t_t[i * 3 + c];

    float x = gamma[h];
    float sp = (x > 20.f) ? x : log1pf(expf(x));
    float g = sp * w_c * 0.5f;

#pragma unroll
    for (int c = 0; c < Cd; ++c) {
        g_qe[(h * DE + c) * NN + i] = g_P[(      c * Hd + h) * NN + i] * 0.25f;
        g_ke[(h * DE + c) * NN + i] = g_P[(192 + c * Hd + h) * NN + i];
    }
    float qn = 0.f, kn = 0.f;
#pragma unroll
    for (int p = 0; p < PQd; ++p) {
        float q0 = g_P[(576 +  0 + h * 4 + p) * NN + i];
        float q1 = g_P[(576 + 48 + h * 4 + p) * NN + i];
        float q2 = g_P[(576 + 96 + h * 4 + p) * NN + i];
        float k0 = g_P[(720 +  0 + h * 4 + p) * NN + i];
        float k1 = g_P[(720 + 48 + h * 4 + p) * NN + i];
        float k2 = g_P[(720 + 96 + h * 4 + p) * NN + i];
#pragma unroll
        for (int co = 0; co < 3; ++co) {
            float qg = R[co * 3] * q0 + R[co * 3 + 1] * q1 + R[co * 3 + 2] * q2 + T[co];
            float kg = R[co * 3] * k0 + R[co * 3 + 1] * k1 + R[co * 3 + 2] * k2 + T[co];
            g_qe[(h * DE + 16 + co * 4 + p) * NN + i] = 2.f * g * qg;
            g_ke[(h * DE + 16 + co * 4 + p) * NN + i] = kg;
            qn += qg * qg;
            kn += kg * kg;
        }
    }
    g_qn[h * NN + i] = g * qn;
    g_kn[h * NN + i] = g * kn;

#pragma unroll
    for (int c = 0; c < Cd; ++c)
        g_vr[(h * Cd + c) * NN + i] = g_P[(384 + c * Hd + h) * NN + i];

#pragma unroll
    for (int p = 0; p < PVd; ++p) {
        float v0 = g_P[(864 +   0 + h * 8 + p) * NN + i];
        float v1 = g_P[(864 +  96 + h * 8 + p) * NN + i];
        float v2 = g_P[(864 + 192 + h * 8 + p) * NN + i];
#pragma unroll
        for (int co = 0; co < 3; ++co)
            g_vg[(co * 96 + h * 8 + p) * NN + i] =
                R[co * 3] * v0 + R[co * 3 + 1] * v1 + R[co * 3 + 2] * v2 + T[co];
    }
}

// ================= fused logits + softmax + o1 : ONE query row per block =================
// smem bytes: S[12][512]f @0 (24576) | W2[128][12]ull @24576 (12288)
//             | QE2[336]ull @36864 (2688) | QN[12]f @39552 (48)
#define FZ_SMEM 39680

__global__ __launch_bounds__(256) void fusedz_kernel(const float* __restrict__ Z,
                                                     const float* __restrict__ Wb) {
    extern __shared__ char smraw[];
    float* S   = (float*)(smraw);
    ull*   W2  = (ull*)(smraw + 24576);
    ull*   QE2 = (ull*)(smraw + 36864);
    float* QN  = (float*)(smraw + 39552);

    const int tid = threadIdx.x;
    const int i = blockIdx.x;
    const float w_l = 0.5773502691896258f;

    for (int t = tid; t < CZd * Hd; t += 256) {
        int h = t % 12, c = t / 12;
        float w = Wb[h * CZd + c];
        W2[t] = pk2(w, w);
    }
    for (int t = tid; t < Hd * DE; t += 256) {
        float v = g_qe[t * NN + i];
        QE2[t] = pk2(v, v);
    }
    if (tid < 12) QN[tid] = g_qn[tid * NN + i];
    __syncthreads();

    const ull* z64  = (const ull*)Z;
    const ull* ke64 = (const ull*)g_ke;
    const ull* kn64 = (const ull*)g_kn;

    ull acc[Hd];
#pragma unroll
    for (int h = 0; h < Hd; ++h) acc[h] = 0ull;

    // ---- Phase A: bias = Wb @ z over c, j-pair per thread ----
    size_t base = (size_t)i * (NN / 2) + tid;
#pragma unroll 2
    for (int c = 0; c < CZd; c += 4) {
        ull z0 = z64[(size_t)(c    ) * (NN * NN / 2) + base];
        ull z1 = z64[(size_t)(c + 1) * (NN * NN / 2) + base];
        ull z2 = z64[(size_t)(c + 2) * (NN * NN / 2) + base];
        ull z3 = z64[(size_t)(c + 3) * (NN * NN / 2) + base];
#pragma unroll
        for (int h = 0; h < Hd; ++h) ffma2(acc[h], W2[(c    ) * 12 + h], z0);
#pragma unroll
        for (int h = 0; h < Hd; ++h) ffma2(acc[h], W2[(c + 1) * 12 + h], z1);
#pragma unroll
        for (int h = 0; h < Hd; ++h) ffma2(acc[h], W2[(c + 2) * 12 + h], z2);
#pragma unroll
        for (int h = 0; h < Hd; ++h) ffma2(acc[h], W2[(c + 3) * 12 + h], z3);
    }

    // ---- qk + distance augmented dot (28 dims per head) ----
#pragma unroll
    for (int h = 0; h < Hd; ++h) {
#pragma unroll 4
        for (int d = 0; d < DE; ++d) {
            ull ke2 = ke64[(size_t)(h * DE + d) * (NN / 2) + tid];
            ffma2(acc[h], QE2[h * DE + d], ke2);
        }
    }

    // ---- logits into smem ----
    int j0 = 2 * tid;
#pragma unroll
    for (int h = 0; h < Hd; ++h) {
        float klo, khi;
        upk2(kn64[h * (NN / 2) + tid], klo, khi);
        float a, b2;
        upk2(acc[h], a, b2);
        S[h * NN + j0]     = w_l * (a  - QN[h] - klo);
        S[h * NN + j0 + 1] = w_l * (b2 - QN[h] - khi);
    }
    __syncthreads();

    // ---- softmax: 12 rows over 8 warps ----
    const int warp = tid >> 5, lane = tid & 31;
    for (int task = warp; task < Hd; task += 8) {
        float* Sr = S + task * NN;
        float m = -1e30f;
#pragma unroll
        for (int k = 0; k < 16; ++k) m = fmaxf(m, Sr[k * 32 + lane]);
#pragma unroll
        for (int o = 16; o; o >>= 1) m = fmaxf(m, __shfl_xor_sync(0xffffffffu, m, o));
        float ssum = 0.f;
#pragma unroll
        for (int k = 0; k < 16; ++k) {
            float e = __expf(Sr[k * 32 + lane] - m);
            Sr[k * 32 + lane] = e;
            ssum += e;
        }
#pragma unroll
        for (int o = 16; o; o >>= 1) ssum += __shfl_xor_sync(0xffffffffu, ssum, o);
        float inv = 1.f / ssum;
#pragma unroll
        for (int k = 0; k < 16; ++k) Sr[k * 32 + lane] *= inv;
    }
    __syncthreads();

    // ---- export probs for o23 ----
    {
        float4* dst = (float4*)(g_A + (size_t)i * Hd * NN);
        const float4* src = (const float4*)S;
        for (int t = tid; t < Hd * NN / 4; t += 256) dst[t] = src[t];
    }

    // ---- Phase B: o1[c,h] = sum_j p[h,j] * z[c,i,j]  (z now L2-resident) ----
    const ull* A64 = (const ull*)S;
    for (int c = warp; c < CZd; c += 8) {
        ull acc1[Hd];
#pragma unroll
        for (int h = 0; h < Hd; ++h) acc1[h] = 0ull;
        size_t zb = (size_t)c * (NN * NN / 2) + (size_t)i * (NN / 2);
#pragma unroll
        for (int k = 0; k < 8; ++k) {
            int jp = k * 32 + lane;
            ull z2 = z64[zb + jp];
#pragma unroll
            for (int h = 0; h < Hd; ++h)
                ffma2(acc1[h], A64[h * (NN / 2) + jp], z2);
        }
#pragma unroll
        for (int h = 0; h < Hd; ++h) {
            float a, b2;
            upk2(acc1[h], a, b2);
            float s = a + b2;
#pragma unroll
            for (int o = 16; o; o >>= 1) s += __shfl_xor_sync(0xffffffffu, s, o);
            if (lane == 0) g_cat[(size_t)(c * Hd + h) * NN + i] = s;
        }
    }
}

// ---------------- o2 + o3 + norm: 4 query rows per block ----------------
#define O23_SMEM 107712

__global__ __launch_bounds__(256) void o23_kernel(const float* __restrict__ t_r,
                                                  const float* __restrict__ t_t) {
    extern __shared__ char smraw[];
    float* As   = (float*)smraw;
    float* o3g  = (float*)(smraw + 98304);
    float* o3l  = (float*)(smraw + 102912);
    float* RS   = (float*)(smraw + 107520);
    float* TS   = (float*)(smraw + 107664);

    const int tid = threadIdx.x;
    const int i0 = blockIdx.x * 4;

    {
        float4* d = (float4*)As;
        const float4* s = (const float4*)(g_A + (size_t)i0 * Hd * NN);
        for (int t = tid; t < 4 * Hd * NN / 4; t += 256) d[t] = s[t];
    }
    if (tid < 36) { int ii = tid / 9; RS[tid] = t_r[(i0 + ii) * 9 + tid % 9]; }
    if (tid < 12) { int ii = tid / 3; TS[tid] = t_t[(i0 + ii) * 3 + tid % 3]; }
    __syncthreads();

    const ull* A64 = (const ull*)As;
    const int warp = tid >> 5, lane = tid & 31;

    for (int r = warp; r < 480; r += 8) {
        const ull* row64;
        int h, rr = 0;
        if (r < 192) { row64 = (const ull*)(g_vr + (size_t)r * NN); h = r >> 4; }
        else { rr = r - 192; row64 = (const ull*)(g_vg + (size_t)rr * NN); h = (rr % 96) >> 3; }

        ull acc[4];
#pragma unroll
        for (int ii = 0; ii < 4; ++ii) acc[ii] = 0ull;
#pragma unroll
        for (int k = 0; k < 8; ++k) {
            int jp = k * 32 + lane;
            ull v2 = row64[jp];
#pragma unroll
            for (int ii = 0; ii < 4; ++ii)
                ffma2(acc[ii], A64[ii * (Hd * NN / 2) + h * (NN / 2) + jp], v2);
        }
#pragma unroll
        for (int ii = 0; ii < 4; ++ii) {
            float a, b2;
            upk2(acc[ii], a, b2);
            float s = a + b2;
#pragma unroll
            for (int o = 16; o; o >>= 1) s += __shfl_xor_sync(0xffffffffu, s, o);
            if (lane == 0) {
                if (r < 192) g_cat[(size_t)(1536 + (r & 15) * Hd + h) * NN + i0 + ii] = s;
                else         o3g[ii * 288 + rr] = s;
            }
        }
    }
    __syncthreads();

    for (int t = tid; t < 4 * 288; t += 256) {
        int ii = t / 288, rr = t % 288;
        int co = rr / 96, hp = rr % 96;
        float v = 0.f;
#pragma unroll
        for (int cj = 0; cj < 3; ++cj)
            v += RS[ii * 9 + cj * 3 + co] * (o3g[ii * 288 + cj * 96 + hp] - TS[ii * 3 + cj]);
        o3l[t] = v;
        g_cat[(size_t)(1728 + rr) * NN + i0 + ii] = v;
    }
    __syncthreads();

    if (warp < 4) {
        int ii = warp;
        float sacc = 0.f;
        for (int r = lane; r < 288; r += 32) {
            float v = o3l[ii * 288 + r];
            sacc += v * v;
        }
#pragma unroll
        for (int o = 16; o; o >>= 1) sacc += __shfl_xor_sync(0xffffffffu, sacc, o);
        if (lane == 0) g_cat[(size_t)2016 * NN + i0 + ii] = sqrtf(sacc);
    }
}

// ---------------- final reduce ----------------
__global__ void reduce_out(const float* __restrict__ bs, float* __restrict__ out) {
    int idx = blockIdx.x * 256 + threadIdx.x;
    if (idx >= CSd * NN) return;
    int o = idx >> 9;
    float v = bs[o];
#pragma unroll
    for (int zk = 0; zk < KSPLIT; ++zk) v += g_part[(size_t)zk * CSd * NN + idx];
    out[idx] = v;
}

// ---------------- launcher ----------------
extern "C" void kernel_launch(void* const* d_in, const int* in_sizes, int n_in,
                              void* d_out, int out_size) {
    const float* s    = (const float*)d_in[0];
    const float* z    = (const float*)d_in[1];
    const float* t_r  = (const float*)d_in[2];
    const float* t_t  = (const float*)d_in[3];
    const float* Wq   = (const float*)d_in[4];
    const float* Wk   = (const float*)d_in[5];
    const float* Wv   = (const float*)d_in[6];
    const float* Wqp  = (const float*)d_in[7];
    const float* Wkp  = (const float*)d_in[8];
    const float* Wvp  = (const float*)d_in[9];
    const float* Wb   = (const float*)d_in[10];
    const float* gam  = (const float*)d_in[11];
    const float* Ws   = (const float*)d_in[12];
    const float* bs   = (const float*)d_in[13];
    float* out = (float*)d_out;

    float *pWcat, *pP, *pCat, *pPart;
    cudaGetSymbolAddress((void**)&pWcat, g_Wcat);
    cudaGetSymbolAddress((void**)&pP,    g_P);
    cudaGetSymbolAddress((void**)&pCat,  g_cat);
    cudaGetSymbolAddress((void**)&pPart, g_part);

    cudaFuncSetAttribute(fusedz_kernel, cudaFuncAttributeMaxDynamicSharedMemorySize, FZ_SMEM);
    cudaFuncSetAttribute(o23_kernel,    cudaFuncAttributeMaxDynamicSharedMemorySize, O23_SMEM);

    concat_w<<<(MPROJ * CSd + 255) / 256, 256>>>(Wq, Wk, Wv, Wqp, Wkp, Wvp);
    gemm64<<<dim3(NN / 64, MPROJ / 64, 1), 256>>>(pWcat, s, pP, MPROJ, NN, CSd);
    prep_kernel<<<(Hd * NN + 255) / 256, 256>>>(t_r, t_t, gam);
    fusedz_kernel<<<NN, 256, FZ_SMEM>>>(z, Wb);
    o23_kernel<<<NN / 4, 256, O23_SMEM>>>(t_r, t_t);
    gemm64<<<dim3(NN / 64, CSd / 64, KSPLIT), 256>>>(Ws, pCat, pPart, CSd, NN, CATd);
    reduce_out<<<(CSd * NN + 255) / 256, 256>>>(bs, out);
}